// round 1
// baseline (speedup 1.0000x reference)
#include <cuda_runtime.h>
#include <math.h>

#define NN 50000
#define EE 1600000
#define TT 12
#define FF 16
#define HH 128
#define OUTD 3
#define HOR 6

// ---------------- scratch (static device globals; no allocation) ----------------
__device__ float g_dinv[NN];
__device__ float g_agg[NN * FF];
__device__ float g_z[NN * HH];
__device__ float g_hr[NN * HH];
__device__ float g_h[NN * HH];
__device__ float g_hw[NN * HH];
__device__ float g_xmod[NN * FF];
__device__ unsigned char g_maskc[TT * NN];
__device__ int g_seen[NN];
__device__ float g_Bzr_top[16 * 256];   // [16,256]  fused Wcz@Wlz_top | Wcr@Wlr_top
__device__ float g_bzr[256];            // fused biases for z|r
__device__ float g_Bzr_bot[128 * 256];  // [128,256] Wlz_bot | Wlr_bot packed
__device__ float g_Bh_top[16 * 128];    // fused Wch@Wlh_top
__device__ float g_bh[128];             // fused bias for h gate
__device__ int g_isbyte;

// ---------------- mask dtype detection + canonicalization ----------------
__global__ void k_detect(const unsigned char* raw) {
    __shared__ int cnt;
    if (threadIdx.x == 0) cnt = 0;
    __syncthreads();
    int c = 0;
    for (int i = threadIdx.x; i < 4096; i += blockDim.x)
        c += (raw[i] != 0);
    atomicAdd(&cnt, c);
    __syncthreads();
    if (threadIdx.x == 0) g_isbyte = (cnt > 2048) ? 1 : 0;
}

__global__ void k_convert(const unsigned char* raw) {
    int i = blockIdx.x * blockDim.x + threadIdx.x;
    if (i >= TT * NN) return;
    if (g_isbyte) g_maskc[i] = raw[i] ? 1 : 0;
    else          g_maskc[i] = (((const int*)raw)[i] != 0) ? 1 : 0;  // int32 or f32 bits
}

// ---------------- weight fusion ----------------
__global__ void k_fuse(const float* __restrict__ Wcz, const float* __restrict__ Wlz,
                       const float* __restrict__ blz, const float* __restrict__ bcz,
                       const float* __restrict__ Wcr, const float* __restrict__ Wlr,
                       const float* __restrict__ blr, const float* __restrict__ bcr,
                       const float* __restrict__ Wch, const float* __restrict__ Wlh,
                       const float* __restrict__ blh, const float* __restrict__ bch) {
    int i = blockIdx.x * blockDim.x + threadIdx.x;
    if (i < 16 * 256) {                           // Bzr_top
        int k = i / 256, c = i % 256, cc = c & 127;
        const float* A = (c < 128) ? Wcz : Wcr;
        const float* B = (c < 128) ? Wlz : Wlr;
        float s = 0.f;
        for (int j = 0; j < 128; ++j) s += A[k * 128 + j] * B[j * 128 + cc];
        g_Bzr_top[i] = s;
    } else if (i < 4096 + 2048) {                 // Bh_top
        int r = i - 4096; int k = r / 128, c = r % 128;
        float s = 0.f;
        for (int j = 0; j < 128; ++j) s += Wch[k * 128 + j] * Wlh[j * 128 + c];
        g_Bh_top[r] = s;
    } else if (i < 6144 + 256) {                  // fused z|r bias
        int c = i - 6144; int cc = c & 127;
        const float* bc = (c < 128) ? bcz : bcr;
        const float* B  = (c < 128) ? Wlz : Wlr;
        const float* bl = (c < 128) ? blz : blr;
        float s = bl[cc];
        for (int j = 0; j < 128; ++j) s += bc[j] * B[j * 128 + cc];
        g_bzr[c] = s;
    } else if (i < 6400 + 128) {                  // fused h bias
        int c = i - 6400;
        float s = blh[c];
        for (int j = 0; j < 128; ++j) s += bch[j] * Wlh[j * 128 + c];
        g_bh[c] = s;
    } else if (i < 6528 + 128 * 256) {            // Bzr_bot pack
        int r = i - 6528; int k = r / 256, c = r % 256;
        g_Bzr_bot[r] = (c < 128) ? Wlz[(128 + k) * 128 + c]
                                 : Wlr[(128 + k) * 128 + (c - 128)];
    }
}

__global__ void k_init() {
    int i = blockIdx.x * blockDim.x + threadIdx.x;
    if (i < NN * HH) g_h[i] = 0.f;
    if (i < NN) g_seen[i] = 0;
}

// ---------------- per-step graph normalization + aggregation ----------------
__global__ void k_step_prep(int t) {  // zero deg; commit previous step's seen-update
    int n = blockIdx.x * blockDim.x + threadIdx.x;
    if (n < NN) {
        g_dinv[n] = 0.f;
        if (t > 0) g_seen[n] |= (int)g_maskc[(t - 1) * NN + n];
    }
}

__global__ void k_deg(const int* __restrict__ ei, const float* __restrict__ ea) {
    int e = blockIdx.x * blockDim.x + threadIdx.x;
    if (e < EE) atomicAdd(&g_dinv[ei[EE + e]], ea[e]);
}

// recompute!=0: dinv = rsqrt(deg + 1 (self loop)); then agg[n] = dinv^2 * x[n]
__global__ void k_dinv_aggself(const float* __restrict__ x, int recompute) {
    int n = blockIdx.x * blockDim.x + threadIdx.x;
    if (n >= NN) return;
    float di;
    if (recompute) { di = rsqrtf(g_dinv[n] + 1.0f); g_dinv[n] = di; }
    else           { di = g_dinv[n]; }
    float s = di * di;
    const float4* xp = (const float4*)(x + (size_t)n * FF);
    float4* op = (float4*)(g_agg + (size_t)n * FF);
    float4 a = xp[0], b = xp[1], c = xp[2], d = xp[3];
    op[0] = make_float4(s * a.x, s * a.y, s * a.z, s * a.w);
    op[1] = make_float4(s * b.x, s * b.y, s * b.z, s * b.w);
    op[2] = make_float4(s * c.x, s * c.y, s * c.z, s * c.w);
    op[3] = make_float4(s * d.x, s * d.y, s * d.z, s * d.w);
}

__global__ void k_scatter(const int* __restrict__ ei, const float* __restrict__ ea,
                          const float* __restrict__ x) {
    int e = blockIdx.x * blockDim.x + threadIdx.x;
    if (e >= EE) return;
    int s = ei[e], d = ei[EE + e];
    float nrm = g_dinv[s] * ea[e] * g_dinv[d];
    const float4* xp = (const float4*)(x + (size_t)s * FF);
    float4 a = xp[0], b = xp[1], c = xp[2], dd = xp[3];
    float* o = g_agg + (size_t)d * FF;
    atomicAdd(o + 0,  nrm * a.x);  atomicAdd(o + 1,  nrm * a.y);
    atomicAdd(o + 2,  nrm * a.z);  atomicAdd(o + 3,  nrm * a.w);
    atomicAdd(o + 4,  nrm * b.x);  atomicAdd(o + 5,  nrm * b.y);
    atomicAdd(o + 6,  nrm * b.z);  atomicAdd(o + 7,  nrm * b.w);
    atomicAdd(o + 8,  nrm * c.x);  atomicAdd(o + 9,  nrm * c.y);
    atomicAdd(o + 10, nrm * c.z);  atomicAdd(o + 11, nrm * c.w);
    atomicAdd(o + 12, nrm * dd.x); atomicAdd(o + 13, nrm * dd.y);
    atomicAdd(o + 14, nrm * dd.z); atomicAdd(o + 15, nrm * dd.w);
}

// ---------------- fused gate GEMMs ----------------
// Tile: 128 nodes x 128 cols, 256 threads, 8x8 per thread, K = 16(agg) + 128(h/hr)

__device__ __forceinline__ float sigmoidf_(float v) {
    return 1.0f / (1.0f + __expf(-v));
}

// D1: z|r = sigmoid([agg | h_eff] @ [Bzr_top;Bzr_bot] + bzr); stores z and hr=h_eff*r
__global__ __launch_bounds__(256) void k_gate_zr(int t, int mode) {
    __shared__ float As[16 * 128];
    __shared__ float Bs[16 * 128];
    int tid = threadIdx.x;
    int n0 = blockIdx.x * 128;
    int c0 = blockIdx.y * 128;  // 0 -> z, 128 -> r
    const float* hsrc = mode ? g_hw : g_h;
    const unsigned char* mk = g_maskc + (size_t)t * NN;

    float acc[8][8];
#pragma unroll
    for (int i = 0; i < 8; ++i)
#pragma unroll
        for (int j = 0; j < 8; ++j) acc[i][j] = 0.f;

    int ty = tid >> 4, tx = tid & 15;
    int lr = tid >> 1, lq = tid & 1;          // A loads: row, quarter
    int bk = tid >> 4, bc = (tid & 15) * 8;   // B loads

    int nA = n0 + lr;
    bool rowValid = (nA < NN);
    bool rowOn = rowValid;
    if (rowValid && mode == 0) rowOn = (mk[nA] && g_seen[nA]);

    for (int chunk = 0; chunk < 9; ++chunk) {
        // ---- load A tile (transposed: As[k][m]) ----
        if (chunk == 0) {
#pragma unroll
            for (int h2 = 0; h2 < 2; ++h2) {
                int kq = lq + 2 * h2;
                float4 v = make_float4(0.f, 0.f, 0.f, 0.f);
                if (rowValid) v = *(const float4*)(g_agg + (size_t)nA * 16 + 4 * kq);
                As[(4 * kq + 0) * 128 + lr] = v.x;
                As[(4 * kq + 1) * 128 + lr] = v.y;
                As[(4 * kq + 2) * 128 + lr] = v.z;
                As[(4 * kq + 3) * 128 + lr] = v.w;
            }
        } else {
            int kb = (chunk - 1) * 16;
#pragma unroll
            for (int h2 = 0; h2 < 2; ++h2) {
                int kq = lq + 2 * h2;
                float4 v = make_float4(0.f, 0.f, 0.f, 0.f);
                if (rowOn) v = *(const float4*)(hsrc + (size_t)nA * HH + kb + 4 * kq);
                As[(4 * kq + 0) * 128 + lr] = v.x;
                As[(4 * kq + 1) * 128 + lr] = v.y;
                As[(4 * kq + 2) * 128 + lr] = v.z;
                As[(4 * kq + 3) * 128 + lr] = v.w;
            }
        }
        // ---- load B tile ----
        {
            const float* Bg = (chunk == 0)
                ? (g_Bzr_top + bk * 256 + c0 + bc)
                : (g_Bzr_bot + ((chunk - 1) * 16 + bk) * 256 + c0 + bc);
            *(float4*)&Bs[bk * 128 + bc]     = *(const float4*)Bg;
            *(float4*)&Bs[bk * 128 + bc + 4] = *(const float4*)(Bg + 4);
        }
        __syncthreads();
#pragma unroll
        for (int kk = 0; kk < 16; ++kk) {
            float ra[8], rb[8];
            *(float4*)ra       = *(float4*)&As[kk * 128 + ty * 8];
            *(float4*)(ra + 4) = *(float4*)&As[kk * 128 + ty * 8 + 4];
            *(float4*)rb       = *(float4*)&Bs[kk * 128 + tx * 8];
            *(float4*)(rb + 4) = *(float4*)&Bs[kk * 128 + tx * 8 + 4];
#pragma unroll
            for (int i = 0; i < 8; ++i)
#pragma unroll
                for (int j = 0; j < 8; ++j) acc[i][j] += ra[i] * rb[j];
        }
        __syncthreads();
    }

    bool isR = (c0 != 0);
#pragma unroll
    for (int i = 0; i < 8; ++i) {
        int n = n0 + ty * 8 + i;
        if (n >= NN) continue;
        bool on = true;
        if (isR && mode == 0) on = (mk[n] && g_seen[n]);
#pragma unroll
        for (int j = 0; j < 8; ++j) {
            int c = tx * 8 + j;
            float s = sigmoidf_(acc[i][j] + g_bzr[c0 + c]);
            if (!isR) {
                g_z[(size_t)n * HH + c] = s;
            } else {
                float heff = on ? hsrc[(size_t)n * HH + c] : 0.f;
                g_hr[(size_t)n * HH + c] = heff * s;
            }
        }
    }
}

// D2: h~ = tanh([agg | hr] @ [Bh_top; Wlh_bot] + bh); h_new = z*h_eff + (1-z)*h~
__global__ __launch_bounds__(256) void k_gate_h(int t, int mode,
                                                const float* __restrict__ Wlh_bot) {
    __shared__ float As[16 * 128];
    __shared__ float Bs[16 * 128];
    int tid = threadIdx.x;
    int n0 = blockIdx.x * 128;
    const float* hsrc = mode ? g_hw : g_h;
    const unsigned char* mk = g_maskc + (size_t)t * NN;

    float acc[8][8];
#pragma unroll
    for (int i = 0; i < 8; ++i)
#pragma unroll
        for (int j = 0; j < 8; ++j) acc[i][j] = 0.f;

    int ty = tid >> 4, tx = tid & 15;
    int lr = tid >> 1, lq = tid & 1;
    int bk = tid >> 4, bc = (tid & 15) * 8;

    int nA = n0 + lr;
    bool rowValid = (nA < NN);

    for (int chunk = 0; chunk < 9; ++chunk) {
        if (chunk == 0) {
#pragma unroll
            for (int h2 = 0; h2 < 2; ++h2) {
                int kq = lq + 2 * h2;
                float4 v = make_float4(0.f, 0.f, 0.f, 0.f);
                if (rowValid) v = *(const float4*)(g_agg + (size_t)nA * 16 + 4 * kq);
                As[(4 * kq + 0) * 128 + lr] = v.x;
                As[(4 * kq + 1) * 128 + lr] = v.y;
                As[(4 * kq + 2) * 128 + lr] = v.z;
                As[(4 * kq + 3) * 128 + lr] = v.w;
            }
        } else {
            int kb = (chunk - 1) * 16;
#pragma unroll
            for (int h2 = 0; h2 < 2; ++h2) {
                int kq = lq + 2 * h2;
                float4 v = make_float4(0.f, 0.f, 0.f, 0.f);
                if (rowValid) v = *(const float4*)(g_hr + (size_t)nA * HH + kb + 4 * kq);
                As[(4 * kq + 0) * 128 + lr] = v.x;
                As[(4 * kq + 1) * 128 + lr] = v.y;
                As[(4 * kq + 2) * 128 + lr] = v.z;
                As[(4 * kq + 3) * 128 + lr] = v.w;
            }
        }
        {
            const float* Bg = (chunk == 0)
                ? (g_Bh_top + bk * 128 + bc)
                : (Wlh_bot + ((size_t)((chunk - 1) * 16 + bk)) * 128 + bc);
            *(float4*)&Bs[bk * 128 + bc]     = *(const float4*)Bg;
            *(float4*)&Bs[bk * 128 + bc + 4] = *(const float4*)(Bg + 4);
        }
        __syncthreads();
#pragma unroll
        for (int kk = 0; kk < 16; ++kk) {
            float ra[8], rb[8];
            *(float4*)ra       = *(float4*)&As[kk * 128 + ty * 8];
            *(float4*)(ra + 4) = *(float4*)&As[kk * 128 + ty * 8 + 4];
            *(float4*)rb       = *(float4*)&Bs[kk * 128 + tx * 8];
            *(float4*)(rb + 4) = *(float4*)&Bs[kk * 128 + tx * 8 + 4];
#pragma unroll
            for (int i = 0; i < 8; ++i)
#pragma unroll
                for (int j = 0; j < 8; ++j) acc[i][j] += ra[i] * rb[j];
        }
        __syncthreads();
    }

#pragma unroll
    for (int i = 0; i < 8; ++i) {
        int n = n0 + ty * 8 + i;
        if (n >= NN) continue;
        bool on = mode ? true : (mk[n] && g_seen[n]);
        bool wr = mode ? true : (mk[n] != 0);
#pragma unroll
        for (int j = 0; j < 8; ++j) {
            int c = tx * 8 + j;
            float ht = tanhf(acc[i][j] + g_bh[c]);
            float zv = g_z[(size_t)n * HH + c];
            float heff = on ? hsrc[(size_t)n * HH + c] : 0.f;
            float hn = zv * heff + (1.f - zv) * ht;
            if (mode) g_hw[(size_t)n * HH + c] = hn;
            else if (wr) g_h[(size_t)n * HH + c] = hn;
        }
    }
}

// ---------------- transition / horizon helpers ----------------
__global__ void k_transition() {
    int i = blockIdx.x * blockDim.x + threadIdx.x;
    if (i >= NN * HH) return;
    int n = i >> 7;
    g_hw[i] = g_maskc[11 * NN + n] ? g_h[i] : 0.f;
}

__global__ void k_xmod(const float* __restrict__ xl, const float* __restrict__ pred) {
    int i = blockIdx.x * blockDim.x + threadIdx.x;
    if (i >= NN * FF) return;
    int n = i >> 4, f = i & 15;
    g_xmod[i] = (f < OUTD) ? pred[n * OUTD + f] : xl[i];
}

__global__ void k_pred(float* __restrict__ outk, const float* __restrict__ W,
                       const float* __restrict__ b) {
    int gt = blockIdx.x * blockDim.x + threadIdx.x;
    int warp = gt >> 5, lane = gt & 31;
    if (warp >= NN) return;
    const float* h = g_hw + (size_t)warp * HH;
    float p0 = 0.f, p1 = 0.f, p2 = 0.f;
#pragma unroll
    for (int i = 0; i < 4; ++i) {
        int c = lane + 32 * i;
        float hv = h[c];
        const float* w = W + c * 3;
        p0 += hv * w[0]; p1 += hv * w[1]; p2 += hv * w[2];
    }
#pragma unroll
    for (int o = 16; o > 0; o >>= 1) {
        p0 += __shfl_xor_sync(0xFFFFFFFFu, p0, o);
        p1 += __shfl_xor_sync(0xFFFFFFFFu, p1, o);
        p2 += __shfl_xor_sync(0xFFFFFFFFu, p2, o);
    }
    if (lane == 0) {
        outk[warp * 3 + 0] = p0 + b[0];
        outk[warp * 3 + 1] = p1 + b[1];
        outk[warp * 3 + 2] = p2 + b[2];
    }
}

// ---------------- launch ----------------
extern "C" void kernel_launch(void* const* d_in, const int* in_sizes, int n_in,
                              void* d_out, int out_size) {
    const float* x_seq = (const float*)d_in[0];
    const int*   ei    = (const int*)d_in[1];
    const float* ea    = (const float*)d_in[2];
    const unsigned char* mraw = (const unsigned char*)d_in[3];
    const float* Wcz = (const float*)d_in[4];
    const float* bcz = (const float*)d_in[5];
    const float* Wlz = (const float*)d_in[6];
    const float* blz = (const float*)d_in[7];
    const float* Wcr = (const float*)d_in[8];
    const float* bcr = (const float*)d_in[9];
    const float* Wlr = (const float*)d_in[10];
    const float* blr = (const float*)d_in[11];
    const float* Wch = (const float*)d_in[12];
    const float* bch = (const float*)d_in[13];
    const float* Wlh = (const float*)d_in[14];
    const float* blh = (const float*)d_in[15];
    const float* hW  = (const float*)d_in[16];
    const float* hb  = (const float*)d_in[17];
    float* out = (float*)d_out;

    void* xmod_p = nullptr;
    cudaGetSymbolAddress(&xmod_p, g_xmod);
    const float* xmod = (const float*)xmod_p;

    const int THR = 256;
    k_detect<<<1, THR>>>(mraw);
    k_convert<<<(TT * NN + THR - 1) / THR, THR>>>(mraw);
    k_fuse<<<(6528 + 128 * 256 + THR - 1) / THR, THR>>>(Wcz, Wlz, blz, bcz,
                                                        Wcr, Wlr, blr, bcr,
                                                        Wch, Wlh, blh, bch);
    k_init<<<(NN * HH + THR - 1) / THR, THR>>>();

    dim3 gZR((NN + 127) / 128, 2), gH((NN + 127) / 128, 1);
    const float* Wlh_bot = Wlh + 128 * 128;

    for (int t = 0; t < TT; ++t) {
        const int*   eit = ei + (size_t)t * 2 * EE;
        const float* eat = ea + (size_t)t * EE;
        const float* xt  = x_seq + (size_t)t * NN * FF;
        k_step_prep<<<(NN + THR - 1) / THR, THR>>>(t);
        k_deg<<<(EE + THR - 1) / THR, THR>>>(eit, eat);
        k_dinv_aggself<<<(NN + THR - 1) / THR, THR>>>(xt, 1);
        k_scatter<<<(EE + THR - 1) / THR, THR>>>(eit, eat, xt);
        k_gate_zr<<<gZR, THR>>>(t, 0);
        k_gate_h<<<gH, THR>>>(t, 0, Wlh_bot);
    }

    k_transition<<<(NN * HH + THR - 1) / THR, THR>>>();

    const int*   eiL = ei + (size_t)11 * 2 * EE;
    const float* eaL = ea + (size_t)11 * EE;
    const float* xL  = x_seq + (size_t)11 * NN * FF;

    for (int k = 0; k < HOR; ++k) {
        const float* xk = xL;
        if (k > 0) {
            k_xmod<<<(NN * FF + THR - 1) / THR, THR>>>(xL, out + (size_t)(k - 1) * NN * OUTD);
            xk = xmod;
        }
        k_dinv_aggself<<<(NN + THR - 1) / THR, THR>>>(xk, 0);
        k_scatter<<<(EE + THR - 1) / THR, THR>>>(eiL, eaL, xk);
        k_gate_zr<<<gZR, THR>>>(11, 1);
        k_gate_h<<<gH, THR>>>(11, 1, Wlh_bot);
        k_pred<<<(NN * 32 + THR - 1) / THR, THR>>>(out + (size_t)k * NN * OUTD, hW, hb);
    }
}

// round 2
// speedup vs baseline: 1.3421x; 1.3421x over previous
#include <cuda_runtime.h>
#include <math.h>

#define NN 50000
#define EE 1600000
#define TT 12
#define FF 16
#define HH 128
#define OUTD 3
#define HOR 6

// ---------------- scratch (static device globals; no allocation) ----------------
__device__ float g_dinv_all[TT * NN];
__device__ float g_agg[NN * FF];
__device__ float g_z[NN * HH];
__device__ float g_hr[NN * HH];
__device__ float g_h[NN * HH];
__device__ float g_hw[NN * HH];
__device__ float g_xmod[NN * FF];
__device__ unsigned char g_maskc[TT * NN];
__device__ unsigned char g_meff[TT * NN];   // mask[t] & (mask[0]|...|mask[t-1])
__device__ float g_Bzr_top[16 * 256];   // [16,256]  fused Wcz@Wlz_top | Wcr@Wlr_top
__device__ float g_bzr[256];            // fused biases for z|r
__device__ float g_Bzr_bot[128 * 256];  // [128,256] Wlz_bot | Wlr_bot packed
__device__ float g_Bh_top[16 * 128];    // fused Wch@Wlh_top
__device__ float g_bh[128];             // fused bias for h gate
__device__ int g_isbyte;

// ---------------- f32x2 packed-FMA helpers (Blackwell FFMA2 pipe) ----------------
__device__ __forceinline__ unsigned long long pack2(float lo, float hi) {
    unsigned long long r;
    asm("mov.b64 %0, {%1, %2};" : "=l"(r) : "f"(lo), "f"(hi));
    return r;
}
__device__ __forceinline__ void fma2(unsigned long long& acc,
                                     unsigned long long a, unsigned long long b) {
    asm("fma.rn.f32x2 %0, %1, %2, %0;" : "+l"(acc) : "l"(a), "l"(b));
}
__device__ __forceinline__ float2 unpack2(unsigned long long v) {
    float2 f;
    asm("mov.b64 {%0, %1}, %2;" : "=f"(f.x), "=f"(f.y) : "l"(v));
    return f;
}

// ---------------- mask dtype detection + canonicalization ----------------
__global__ void k_detect(const unsigned char* raw) {
    __shared__ int cnt;
    if (threadIdx.x == 0) cnt = 0;
    __syncthreads();
    int c = 0;
    for (int i = threadIdx.x; i < 4096; i += blockDim.x)
        c += (raw[i] != 0);
    atomicAdd(&cnt, c);
    __syncthreads();
    if (threadIdx.x == 0) g_isbyte = (cnt > 2048) ? 1 : 0;
}

// per node: canonical masks + prefix "mask & seen_before"
__global__ void k_convert(const unsigned char* raw) {
    int n = blockIdx.x * blockDim.x + threadIdx.x;
    if (n >= NN) return;
    int isb = g_isbyte;
    int seen = 0;
#pragma unroll
    for (int t = 0; t < TT; ++t) {
        int m = isb ? (raw[t * NN + n] != 0)
                    : (((const int*)raw)[t * NN + n] != 0);
        g_maskc[t * NN + n] = (unsigned char)m;
        g_meff[t * NN + n] = (unsigned char)(m & seen);
        seen |= m;
    }
}

// ---------------- weight fusion ----------------
__global__ void k_fuse(const float* __restrict__ Wcz, const float* __restrict__ Wlz,
                       const float* __restrict__ blz, const float* __restrict__ bcz,
                       const float* __restrict__ Wcr, const float* __restrict__ Wlr,
                       const float* __restrict__ blr, const float* __restrict__ bcr,
                       const float* __restrict__ Wch, const float* __restrict__ Wlh,
                       const float* __restrict__ blh, const float* __restrict__ bch) {
    int i = blockIdx.x * blockDim.x + threadIdx.x;
    if (i < 16 * 256) {                           // Bzr_top
        int k = i / 256, c = i % 256, cc = c & 127;
        const float* A = (c < 128) ? Wcz : Wcr;
        const float* B = (c < 128) ? Wlz : Wlr;
        float s = 0.f;
        for (int j = 0; j < 128; ++j) s += A[k * 128 + j] * B[j * 128 + cc];
        g_Bzr_top[i] = s;
    } else if (i < 4096 + 2048) {                 // Bh_top
        int r = i - 4096; int k = r / 128, c = r % 128;
        float s = 0.f;
        for (int j = 0; j < 128; ++j) s += Wch[k * 128 + j] * Wlh[j * 128 + c];
        g_Bh_top[r] = s;
    } else if (i < 6144 + 256) {                  // fused z|r bias
        int c = i - 6144; int cc = c & 127;
        const float* bc = (c < 128) ? bcz : bcr;
        const float* B  = (c < 128) ? Wlz : Wlr;
        const float* bl = (c < 128) ? blz : blr;
        float s = bl[cc];
        for (int j = 0; j < 128; ++j) s += bc[j] * B[j * 128 + cc];
        g_bzr[c] = s;
    } else if (i < 6400 + 128) {                  // fused h bias
        int c = i - 6400;
        float s = blh[c];
        for (int j = 0; j < 128; ++j) s += bch[j] * Wlh[j * 128 + c];
        g_bh[c] = s;
    } else if (i < 6528 + 128 * 256) {            // Bzr_bot pack
        int r = i - 6528; int k = r / 256, c = r % 256;
        g_Bzr_bot[r] = (c < 128) ? Wlz[(128 + k) * 128 + c]
                                 : Wlr[(128 + k) * 128 + (c - 128)];
    }
}

__global__ void k_init() {
    int i = blockIdx.x * blockDim.x + threadIdx.x;
    if (i < NN * HH) g_h[i] = 0.f;
    if (i < TT * NN) g_dinv_all[i] = 0.f;
}

// ---------------- degree / dinv precompute (all 12 graphs, batched) ----------------
__global__ void k_deg_all(const int* __restrict__ ei, const float* __restrict__ ea) {
    int e = blockIdx.x * blockDim.x + threadIdx.x;
    if (e >= TT * EE) return;
    int t = e / EE, le = e - t * EE;
    int dst = ei[(size_t)t * 2 * EE + EE + le];
    atomicAdd(&g_dinv_all[t * NN + dst], ea[(size_t)t * EE + le]);
}

__global__ void k_dinv_fin() {
    int i = blockIdx.x * blockDim.x + threadIdx.x;
    if (i < TT * NN) g_dinv_all[i] = rsqrtf(g_dinv_all[i] + 1.0f);  // +1 self loop
}

// agg[n] = dinv[n]^2 * x[n]  (self-loop term; also inits g_agg)
__global__ void k_aggself(const float* __restrict__ x, const float* __restrict__ dinv) {
    int n = blockIdx.x * blockDim.x + threadIdx.x;
    if (n >= NN) return;
    float di = dinv[n];
    float s = di * di;
    const float4* xp = (const float4*)(x + (size_t)n * FF);
    float4* op = (float4*)(g_agg + (size_t)n * FF);
    float4 a = xp[0], b = xp[1], c = xp[2], d = xp[3];
    op[0] = make_float4(s * a.x, s * a.y, s * a.z, s * a.w);
    op[1] = make_float4(s * b.x, s * b.y, s * b.z, s * b.w);
    op[2] = make_float4(s * c.x, s * c.y, s * c.z, s * c.w);
    op[3] = make_float4(s * d.x, s * d.y, s * d.z, s * d.w);
}

#define REDV4(p, a, b, c, d)                                              \
    asm volatile("red.global.add.v4.f32 [%0], {%1,%2,%3,%4};"             \
                 :: "l"(p), "f"(a), "f"(b), "f"(c), "f"(d) : "memory")

__global__ void k_scatter(const int* __restrict__ ei, const float* __restrict__ ea,
                          const float* __restrict__ x, const float* __restrict__ dinv) {
    int e = blockIdx.x * blockDim.x + threadIdx.x;
    if (e >= EE) return;
    int s = ei[e], d = ei[EE + e];
    float nrm = dinv[s] * ea[e] * dinv[d];
    const float4* xp = (const float4*)(x + (size_t)s * FF);
    float4 a = xp[0], b = xp[1], c = xp[2], dd = xp[3];
    float* o = g_agg + (size_t)d * FF;
    REDV4(o + 0,  nrm * a.x,  nrm * a.y,  nrm * a.z,  nrm * a.w);
    REDV4(o + 4,  nrm * b.x,  nrm * b.y,  nrm * b.z,  nrm * b.w);
    REDV4(o + 8,  nrm * c.x,  nrm * c.y,  nrm * c.z,  nrm * c.w);
    REDV4(o + 12, nrm * dd.x, nrm * dd.y, nrm * dd.z, nrm * dd.w);
}

// ---------------- fused gate GEMMs ----------------
// Tile: 128 nodes x 128 cols, 256 threads, 8x8 per thread (f32x2 packed FMA),
// K = 16(agg) + 128(h/hr)

__device__ __forceinline__ float sigmoidf_(float v) {
    return 1.0f / (1.0f + __expf(-v));
}

// D1: z|r = sigmoid([agg | h_eff] @ [Bzr_top;Bzr_bot] + bzr); stores z and hr=h_eff*r
__global__ __launch_bounds__(256) void k_gate_zr(int t, int mode) {
    __shared__ __align__(16) float As[16 * 128];
    __shared__ __align__(16) float Bs[16 * 128];
    int tid = threadIdx.x;
    int n0 = blockIdx.x * 128;
    int c0 = blockIdx.y * 128;  // 0 -> z, 128 -> r
    const float* hsrc = mode ? g_hw : g_h;
    const unsigned char* me = g_meff + (size_t)t * NN;

    unsigned long long accp[8][4];
#pragma unroll
    for (int i = 0; i < 8; ++i)
#pragma unroll
        for (int j = 0; j < 4; ++j) accp[i][j] = 0ull;

    int ty = tid >> 4, tx = tid & 15;
    int lr = tid >> 1, lq = tid & 1;          // A loads: row, quarter
    int bk = tid >> 4, bc = (tid & 15) * 8;   // B loads

    int nA = n0 + lr;
    bool rowValid = (nA < NN);
    bool rowOn = rowValid;
    if (rowValid && mode == 0) rowOn = (me[nA] != 0);

    for (int chunk = 0; chunk < 9; ++chunk) {
        // ---- load A tile (transposed: As[k][m]) ----
        if (chunk == 0) {
#pragma unroll
            for (int h2 = 0; h2 < 2; ++h2) {
                int kq = lq + 2 * h2;
                float4 v = make_float4(0.f, 0.f, 0.f, 0.f);
                if (rowValid) v = *(const float4*)(g_agg + (size_t)nA * 16 + 4 * kq);
                As[(4 * kq + 0) * 128 + lr] = v.x;
                As[(4 * kq + 1) * 128 + lr] = v.y;
                As[(4 * kq + 2) * 128 + lr] = v.z;
                As[(4 * kq + 3) * 128 + lr] = v.w;
            }
        } else {
            int kb = (chunk - 1) * 16;
#pragma unroll
            for (int h2 = 0; h2 < 2; ++h2) {
                int kq = lq + 2 * h2;
                float4 v = make_float4(0.f, 0.f, 0.f, 0.f);
                if (rowOn) v = *(const float4*)(hsrc + (size_t)nA * HH + kb + 4 * kq);
                As[(4 * kq + 0) * 128 + lr] = v.x;
                As[(4 * kq + 1) * 128 + lr] = v.y;
                As[(4 * kq + 2) * 128 + lr] = v.z;
                As[(4 * kq + 3) * 128 + lr] = v.w;
            }
        }
        // ---- load B tile ----
        {
            const float* Bg = (chunk == 0)
                ? (g_Bzr_top + bk * 256 + c0 + bc)
                : (g_Bzr_bot + ((chunk - 1) * 16 + bk) * 256 + c0 + bc);
            *(float4*)&Bs[bk * 128 + bc]     = *(const float4*)Bg;
            *(float4*)&Bs[bk * 128 + bc + 4] = *(const float4*)(Bg + 4);
        }
        __syncthreads();
#pragma unroll
        for (int kk = 0; kk < 16; ++kk) {
            float ra[8];
            *(float4*)ra       = *(float4*)&As[kk * 128 + ty * 8];
            *(float4*)(ra + 4) = *(float4*)&As[kk * 128 + ty * 8 + 4];
            ulonglong2 b01 = *(ulonglong2*)&Bs[kk * 128 + tx * 8];
            ulonglong2 b23 = *(ulonglong2*)&Bs[kk * 128 + tx * 8 + 4];
            unsigned long long rbp[4] = {b01.x, b01.y, b23.x, b23.y};
#pragma unroll
            for (int i = 0; i < 8; ++i) {
                unsigned long long rap = pack2(ra[i], ra[i]);
                fma2(accp[i][0], rap, rbp[0]);
                fma2(accp[i][1], rap, rbp[1]);
                fma2(accp[i][2], rap, rbp[2]);
                fma2(accp[i][3], rap, rbp[3]);
            }
        }
        __syncthreads();
    }

    bool isR = (c0 != 0);
#pragma unroll
    for (int i = 0; i < 8; ++i) {
        int n = n0 + ty * 8 + i;
        if (n >= NN) continue;
        bool on = true;
        if (isR && mode == 0) on = (me[n] != 0);
#pragma unroll
        for (int jp = 0; jp < 4; ++jp) {
            float2 v = unpack2(accp[i][jp]);
            int c = tx * 8 + 2 * jp;
            float s0 = sigmoidf_(v.x + g_bzr[c0 + c]);
            float s1 = sigmoidf_(v.y + g_bzr[c0 + c + 1]);
            if (!isR) {
                g_z[(size_t)n * HH + c]     = s0;
                g_z[(size_t)n * HH + c + 1] = s1;
            } else {
                float h0 = on ? hsrc[(size_t)n * HH + c]     : 0.f;
                float h1 = on ? hsrc[(size_t)n * HH + c + 1] : 0.f;
                g_hr[(size_t)n * HH + c]     = h0 * s0;
                g_hr[(size_t)n * HH + c + 1] = h1 * s1;
            }
        }
    }
}

// D2: h~ = tanh([agg | hr] @ [Bh_top; Wlh_bot] + bh); h_new = z*h_eff + (1-z)*h~
__global__ __launch_bounds__(256) void k_gate_h(int t, int mode,
                                                const float* __restrict__ Wlh_bot) {
    __shared__ __align__(16) float As[16 * 128];
    __shared__ __align__(16) float Bs[16 * 128];
    int tid = threadIdx.x;
    int n0 = blockIdx.x * 128;
    const float* hsrc = mode ? g_hw : g_h;
    const unsigned char* me = g_meff + (size_t)t * NN;
    const unsigned char* mk = g_maskc + (size_t)t * NN;

    unsigned long long accp[8][4];
#pragma unroll
    for (int i = 0; i < 8; ++i)
#pragma unroll
        for (int j = 0; j < 4; ++j) accp[i][j] = 0ull;

    int ty = tid >> 4, tx = tid & 15;
    int lr = tid >> 1, lq = tid & 1;
    int bk = tid >> 4, bc = (tid & 15) * 8;

    int nA = n0 + lr;
    bool rowValid = (nA < NN);

    for (int chunk = 0; chunk < 9; ++chunk) {
        if (chunk == 0) {
#pragma unroll
            for (int h2 = 0; h2 < 2; ++h2) {
                int kq = lq + 2 * h2;
                float4 v = make_float4(0.f, 0.f, 0.f, 0.f);
                if (rowValid) v = *(const float4*)(g_agg + (size_t)nA * 16 + 4 * kq);
                As[(4 * kq + 0) * 128 + lr] = v.x;
                As[(4 * kq + 1) * 128 + lr] = v.y;
                As[(4 * kq + 2) * 128 + lr] = v.z;
                As[(4 * kq + 3) * 128 + lr] = v.w;
            }
        } else {
            int kb = (chunk - 1) * 16;
#pragma unroll
            for (int h2 = 0; h2 < 2; ++h2) {
                int kq = lq + 2 * h2;
                float4 v = make_float4(0.f, 0.f, 0.f, 0.f);
                if (rowValid) v = *(const float4*)(g_hr + (size_t)nA * HH + kb + 4 * kq);
                As[(4 * kq + 0) * 128 + lr] = v.x;
                As[(4 * kq + 1) * 128 + lr] = v.y;
                As[(4 * kq + 2) * 128 + lr] = v.z;
                As[(4 * kq + 3) * 128 + lr] = v.w;
            }
        }
        {
            const float* Bg = (chunk == 0)
                ? (g_Bh_top + bk * 128 + bc)
                : (Wlh_bot + ((size_t)((chunk - 1) * 16 + bk)) * 128 + bc);
            *(float4*)&Bs[bk * 128 + bc]     = *(const float4*)Bg;
            *(float4*)&Bs[bk * 128 + bc + 4] = *(const float4*)(Bg + 4);
        }
        __syncthreads();
#pragma unroll
        for (int kk = 0; kk < 16; ++kk) {
            float ra[8];
            *(float4*)ra       = *(float4*)&As[kk * 128 + ty * 8];
            *(float4*)(ra + 4) = *(float4*)&As[kk * 128 + ty * 8 + 4];
            ulonglong2 b01 = *(ulonglong2*)&Bs[kk * 128 + tx * 8];
            ulonglong2 b23 = *(ulonglong2*)&Bs[kk * 128 + tx * 8 + 4];
            unsigned long long rbp[4] = {b01.x, b01.y, b23.x, b23.y};
#pragma unroll
            for (int i = 0; i < 8; ++i) {
                unsigned long long rap = pack2(ra[i], ra[i]);
                fma2(accp[i][0], rap, rbp[0]);
                fma2(accp[i][1], rap, rbp[1]);
                fma2(accp[i][2], rap, rbp[2]);
                fma2(accp[i][3], rap, rbp[3]);
            }
        }
        __syncthreads();
    }

#pragma unroll
    for (int i = 0; i < 8; ++i) {
        int n = n0 + ty * 8 + i;
        if (n >= NN) continue;
        bool on = mode ? true : (me[n] != 0);
        bool wr = mode ? true : (mk[n] != 0);
#pragma unroll
        for (int jp = 0; jp < 4; ++jp) {
            float2 v = unpack2(accp[i][jp]);
            int c = tx * 8 + 2 * jp;
#pragma unroll
            for (int u = 0; u < 2; ++u) {
                float val = (u == 0) ? v.x : v.y;
                int cc = c + u;
                float ht = tanhf(val + g_bh[cc]);
                float zv = g_z[(size_t)n * HH + cc];
                float heff = on ? hsrc[(size_t)n * HH + cc] : 0.f;
                float hn = zv * heff + (1.f - zv) * ht;
                if (mode) g_hw[(size_t)n * HH + cc] = hn;
                else if (wr) g_h[(size_t)n * HH + cc] = hn;
            }
        }
    }
}

// ---------------- transition / horizon helpers ----------------
__global__ void k_transition() {
    int i = blockIdx.x * blockDim.x + threadIdx.x;
    if (i >= NN * HH) return;
    int n = i >> 7;
    g_hw[i] = g_maskc[11 * NN + n] ? g_h[i] : 0.f;
}

__global__ void k_xmod(const float* __restrict__ xl, const float* __restrict__ pred) {
    int i = blockIdx.x * blockDim.x + threadIdx.x;
    if (i >= NN * FF) return;
    int n = i >> 4, f = i & 15;
    g_xmod[i] = (f < OUTD) ? pred[n * OUTD + f] : xl[i];
}

__global__ void k_pred(float* __restrict__ outk, const float* __restrict__ W,
                       const float* __restrict__ b) {
    int gt = blockIdx.x * blockDim.x + threadIdx.x;
    int warp = gt >> 5, lane = gt & 31;
    if (warp >= NN) return;
    const float* h = g_hw + (size_t)warp * HH;
    float p0 = 0.f, p1 = 0.f, p2 = 0.f;
#pragma unroll
    for (int i = 0; i < 4; ++i) {
        int c = lane + 32 * i;
        float hv = h[c];
        const float* w = W + c * 3;
        p0 += hv * w[0]; p1 += hv * w[1]; p2 += hv * w[2];
    }
#pragma unroll
    for (int o = 16; o > 0; o >>= 1) {
        p0 += __shfl_xor_sync(0xFFFFFFFFu, p0, o);
        p1 += __shfl_xor_sync(0xFFFFFFFFu, p1, o);
        p2 += __shfl_xor_sync(0xFFFFFFFFu, p2, o);
    }
    if (lane == 0) {
        outk[warp * 3 + 0] = p0 + b[0];
        outk[warp * 3 + 1] = p1 + b[1];
        outk[warp * 3 + 2] = p2 + b[2];
    }
}

// ---------------- launch ----------------
extern "C" void kernel_launch(void* const* d_in, const int* in_sizes, int n_in,
                              void* d_out, int out_size) {
    const float* x_seq = (const float*)d_in[0];
    const int*   ei    = (const int*)d_in[1];
    const float* ea    = (const float*)d_in[2];
    const unsigned char* mraw = (const unsigned char*)d_in[3];
    const float* Wcz = (const float*)d_in[4];
    const float* bcz = (const float*)d_in[5];
    const float* Wlz = (const float*)d_in[6];
    const float* blz = (const float*)d_in[7];
    const float* Wcr = (const float*)d_in[8];
    const float* bcr = (const float*)d_in[9];
    const float* Wlr = (const float*)d_in[10];
    const float* blr = (const float*)d_in[11];
    const float* Wch = (const float*)d_in[12];
    const float* bch = (const float*)d_in[13];
    const float* Wlh = (const float*)d_in[14];
    const float* blh = (const float*)d_in[15];
    const float* hW  = (const float*)d_in[16];
    const float* hb  = (const float*)d_in[17];
    float* out = (float*)d_out;

    void* xmod_p = nullptr;
    cudaGetSymbolAddress(&xmod_p, g_xmod);
    const float* xmod = (const float*)xmod_p;
    void* dinv_p = nullptr;
    cudaGetSymbolAddress(&dinv_p, g_dinv_all);
    const float* dinv_all = (const float*)dinv_p;

    const int THR = 256;
    k_detect<<<1, THR>>>(mraw);
    k_convert<<<(NN + THR - 1) / THR, THR>>>(mraw);
    k_fuse<<<(6528 + 128 * 256 + THR - 1) / THR, THR>>>(Wcz, Wlz, blz, bcz,
                                                        Wcr, Wlr, blr, bcr,
                                                        Wch, Wlh, blh, bch);
    k_init<<<(NN * HH + THR - 1) / THR, THR>>>();
    k_deg_all<<<(TT * EE + THR - 1) / THR, THR>>>(ei, ea);
    k_dinv_fin<<<(TT * NN + THR - 1) / THR, THR>>>();

    dim3 gZR((NN + 127) / 128, 2), gH((NN + 127) / 128, 1);
    const float* Wlh_bot = Wlh + 128 * 128;

    for (int t = 0; t < TT; ++t) {
        const int*   eit = ei + (size_t)t * 2 * EE;
        const float* eat = ea + (size_t)t * EE;
        const float* xt  = x_seq + (size_t)t * NN * FF;
        const float* dvt = dinv_all + (size_t)t * NN;
        k_aggself<<<(NN + THR - 1) / THR, THR>>>(xt, dvt);
        k_scatter<<<(EE + THR - 1) / THR, THR>>>(eit, eat, xt, dvt);
        k_gate_zr<<<gZR, THR>>>(t, 0);
        k_gate_h<<<gH, THR>>>(t, 0, Wlh_bot);
    }

    k_transition<<<(NN * HH + THR - 1) / THR, THR>>>();

    const int*   eiL = ei + (size_t)11 * 2 * EE;
    const float* eaL = ea + (size_t)11 * EE;
    const float* xL  = x_seq + (size_t)11 * NN * FF;
    const float* dvL = dinv_all + (size_t)11 * NN;

    for (int k = 0; k < HOR; ++k) {
        const float* xk = xL;
        if (k > 0) {
            k_xmod<<<(NN * FF + THR - 1) / THR, THR>>>(xL, out + (size_t)(k - 1) * NN * OUTD);
            xk = xmod;
        }
        k_aggself<<<(NN + THR - 1) / THR, THR>>>(xk, dvL);
        k_scatter<<<(EE + THR - 1) / THR, THR>>>(eiL, eaL, xk, dvL);
        k_gate_zr<<<gZR, THR>>>(11, 1);
        k_gate_h<<<gH, THR>>>(11, 1, Wlh_bot);
        k_pred<<<(NN * 32 + THR - 1) / THR, THR>>>(out + (size_t)k * NN * OUTD, hW, hb);
    }
}